// round 14
// baseline (speedup 1.0000x reference)
#include <cuda_runtime.h>
#include <cuda_fp16.h>
#include <cuda_bf16.h>
#include <cstdint>
#include <cstddef>

#define TT   4096
#define HID  2048
#define INW  2048
#define G4   (4*HID)

#define NCTA     148
#define HPC      14
#define NROWS    (HPC*4)          // 56 rows per CTA
#define RTHREADS 256              // 8 warps; each owns 7 rows
#define RPW      7
#define NCOPY    8
#define REC_SMEM (NROWS*HID*2 + 256)   // W rows + 56-float sum staging

// ---------------- scratch layout ----------------
#define OFF_GX    ((size_t)0)                            // float [T][4H]
#define OFF_XH    (OFF_GX   + (size_t)TT*G4*4)           // half  [T][I] hi
#define OFF_XL    (OFF_XH   + (size_t)TT*INW*2)          // half  [T][I] lo
#define OFF_WIH   (OFF_XL   + (size_t)TT*INW*2)          // half  [4H][I] hi
#define OFF_WIL   (OFF_WIH  + (size_t)G4*INW*2)          // half  [4H][I] lo
#define OFF_WO    (OFF_WIL  + (size_t)G4*INW*2)          // half  [I][H] hi
#define OFF_HS    (OFF_WO   + (size_t)INW*HID*2)         // half  [T][H]
#define OFF_BIAS  (OFF_HS   + (size_t)TT*HID*2)          // float [4H]
#define OFF_HBUF  (OFF_BIAS + (size_t)G4*4)              // float [2][NCOPY][H]
#define OFF_BAR   (OFF_HBUF + (size_t)2*NCOPY*HID*4)     // counter area
#define SCRATCH_BYTES (OFF_BAR + 4096)

__device__ __align__(256) unsigned char g_scratch[SCRATCH_BYTES];

__device__ __forceinline__ float sigf(float x){ return 1.0f / (1.0f + __expf(-x)); }
__device__ __forceinline__ float tanh_fast(float x){
    float e = __expf(2.0f * x);              // inf-safe: e=inf -> 1; e=0 -> -1
    return 1.0f - 2.0f / (e + 1.0f);
}
__device__ __forceinline__ void red_release_add(unsigned* p){
    asm volatile("red.release.gpu.global.add.u32 [%0], 1;" :: "l"(p) : "memory");
}
__device__ __forceinline__ unsigned ld_acquire(const unsigned* p){
    unsigned v;
    asm volatile("ld.acquire.gpu.global.u32 %0, [%1];" : "=r"(v) : "l"(p) : "memory");
    return v;
}
__device__ __forceinline__ __half2 u2h2(unsigned u){
    __half2 h; *reinterpret_cast<unsigned*>(&h) = u; return h;
}

// ---------------- conversion / setup ----------------
__global__ void f2h_split_kernel(const float* __restrict__ in, __half* __restrict__ hi,
                                 __half* __restrict__ lo, int n){
    int i = (blockIdx.x * blockDim.x + threadIdx.x) * 4;
    int stride = gridDim.x * blockDim.x * 4;
    for (; i < n; i += stride){
        float4 v = *(const float4*)(in + i);
        __half h0 = __float2half_rn(v.x), h1 = __float2half_rn(v.y);
        __half h2 = __float2half_rn(v.z), h3 = __float2half_rn(v.w);
        ((__half2*)(hi + i))[0] = __halves2half2(h0, h1);
        ((__half2*)(hi + i))[1] = __halves2half2(h2, h3);
        ((__half2*)(lo + i))[0] = __halves2half2(
            __float2half_rn(v.x - __half2float(h0)), __float2half_rn(v.y - __half2float(h1)));
        ((__half2*)(lo + i))[1] = __halves2half2(
            __float2half_rn(v.z - __half2float(h2)), __float2half_rn(v.w - __half2float(h3)));
    }
}

__global__ void setup_kernel(const float* __restrict__ a, const float* __restrict__ b,
                             float* __restrict__ o, unsigned* __restrict__ bar){
    int i = blockIdx.x * blockDim.x + threadIdx.x;
    if (i < G4) o[i] = a[i] + b[i];
    if (blockIdx.x == 0 && threadIdx.x < 1024) bar[threadIdx.x] = 0u;
}

// ---------------- fp16 NT GEMM (mma.sync, f32 accum) ----------------
__device__ __forceinline__ void cp_async16(void* smem, const void* g){
    unsigned s = (unsigned)__cvta_generic_to_shared(smem);
    asm volatile("cp.async.cg.shared.global [%0], [%1], 16;\n" :: "r"(s), "l"(g));
}
__device__ __forceinline__ void cp_commit(){ asm volatile("cp.async.commit_group;\n"); }
template<int N> __device__ __forceinline__ void cp_wait(){
    asm volatile("cp.async.wait_group %0;\n" :: "n"(N));
}
__device__ __forceinline__ void mma16816(float* c, const unsigned* a, const unsigned* b){
    asm volatile(
        "mma.sync.aligned.m16n8k16.row.col.f32.f16.f16.f32 "
        "{%0,%1,%2,%3}, {%4,%5,%6,%7}, {%8,%9}, {%0,%1,%2,%3};"
        : "+f"(c[0]), "+f"(c[1]), "+f"(c[2]), "+f"(c[3])
        : "r"(a[0]), "r"(a[1]), "r"(a[2]), "r"(a[3]), "r"(b[0]), "r"(b[1]));
}

#define GSTRIDE 40   // halves per smem row: 32 data + 8 pad (80B, 16B aligned)

template<int SIG, int ACC>
__global__ __launch_bounds__(256, 1)
void gemm_nt_kernel(const __half* __restrict__ A, const __half* __restrict__ B,
                    const float* __restrict__ bias, float* __restrict__ C,
                    int M, int N, int K){
    __shared__ __half As[2][128 * GSTRIDE];
    __shared__ __half Bs[2][128 * GSTRIDE];
    const int tid = threadIdx.x, wid = tid >> 5, l = tid & 31;
    const int wm = wid & 1, wn = wid >> 1;            // 2x4 warps, 64x32 warp tile
    const int m0 = blockIdx.y * 128, n0 = blockIdx.x * 128;

    float acc[4][4][4];
    #pragma unroll
    for (int i = 0; i < 4; ++i)
        #pragma unroll
        for (int j = 0; j < 4; ++j)
            #pragma unroll
            for (int q = 0; q < 4; ++q) acc[i][j][q] = 0.0f;

    const int NT = K / 32;
    auto load_stage = [&](int s, int kt){
        #pragma unroll
        for (int i = 0; i < 2; ++i){
            int c = tid + i * 256;
            int r = c >> 2, ch = c & 3;
            cp_async16(&As[s][r * GSTRIDE + ch * 8], A + (size_t)(m0 + r) * K + kt + ch * 8);
            cp_async16(&Bs[s][r * GSTRIDE + ch * 8], B + (size_t)(n0 + r) * K + kt + ch * 8);
        }
        cp_commit();
    };

    load_stage(0, 0);
    for (int t = 0; t < NT; ++t){
        if (t + 1 < NT){ load_stage((t + 1) & 1, (t + 1) * 32); cp_wait<1>(); }
        else           { cp_wait<0>(); }
        __syncthreads();
        const __half* Asb = As[t & 1];
        const __half* Bsb = Bs[t & 1];
        #pragma unroll
        for (int k16 = 0; k16 < 2; ++k16){
            unsigned a[4][4], b[4][2];
            const int cc = k16 * 16 + (l & 3) * 2;
            #pragma unroll
            for (int i = 0; i < 4; ++i){
                int r = wm * 64 + i * 16 + (l >> 2);
                a[i][0] = *(const unsigned*)(Asb + r * GSTRIDE + cc);
                a[i][1] = *(const unsigned*)(Asb + (r + 8) * GSTRIDE + cc);
                a[i][2] = *(const unsigned*)(Asb + r * GSTRIDE + cc + 8);
                a[i][3] = *(const unsigned*)(Asb + (r + 8) * GSTRIDE + cc + 8);
            }
            #pragma unroll
            for (int j = 0; j < 4; ++j){
                int r = wn * 32 + j * 8 + (l >> 2);
                b[j][0] = *(const unsigned*)(Bsb + r * GSTRIDE + cc);
                b[j][1] = *(const unsigned*)(Bsb + r * GSTRIDE + cc + 8);
            }
            #pragma unroll
            for (int i = 0; i < 4; ++i)
                #pragma unroll
                for (int j = 0; j < 4; ++j)
                    mma16816(acc[i][j], a[i], b[j]);
        }
        __syncthreads();
    }

    #pragma unroll
    for (int i = 0; i < 4; ++i){
        #pragma unroll
        for (int j = 0; j < 4; ++j){
            int rm = m0 + wm * 64 + i * 16 + (l >> 2);
            int cn = n0 + wn * 32 + j * 8 + (l & 3) * 2;
            float2* p0 = (float2*)(C + (size_t)rm * N + cn);
            float2* p1 = (float2*)(C + (size_t)(rm + 8) * N + cn);
            float v0, v1, v2, v3;
            if (ACC){
                float2 o0 = *p0, o1 = *p1;
                v0 = acc[i][j][0] + o0.x; v1 = acc[i][j][1] + o0.y;
                v2 = acc[i][j][2] + o1.x; v3 = acc[i][j][3] + o1.y;
            } else {
                float b0 = bias[cn], b1 = bias[cn + 1];
                v0 = acc[i][j][0] + b0; v1 = acc[i][j][1] + b1;
                v2 = acc[i][j][2] + b0; v3 = acc[i][j][3] + b1;
                if (SIG){ v0 = sigf(v0); v1 = sigf(v1); v2 = sigf(v2); v3 = sigf(v3); }
            }
            *p0 = make_float2(v0, v1);
            *p1 = make_float2(v2, v3);
        }
    }
}

// ---------------- persistent LSTM recurrence ----------------
// 148 CTAs (1/SM), 256 threads = 8 warps (2 per SMSP -> balanced FMA pipes).
// Warp w computes dot products for ROWS [7w, 7w+7) (rows decoupled from
// elements); reduced row sums staged in SMEM; warps 0-6 then apply gate math
// for elements {2w, 2w+1} (c-state mapping unchanged from prior rounds).
// W: K[0,1024) in registers (112 half2/lane), K[1024,2048) streamed from SMEM.
__global__ __launch_bounds__(RTHREADS, 1)
void lstm_rec_kernel(const float* __restrict__ Whh, const float* __restrict__ gx,
                     __half* __restrict__ hs, float* __restrict__ hbuf,
                     unsigned* __restrict__ bar){
    extern __shared__ uint2 smW2[];                   // [56][512] uint2 = 2048 fp16/row
    unsigned* smw32 = (unsigned*)smW2;
    float* smSum = (float*)((char*)smW2 + NROWS * HID * 2);   // 56 floats
    const int tid = threadIdx.x;
    const int w = tid >> 5, l = tid & 31;
    const int cta = blockIdx.x;

    // load + convert this CTA's W_hh rows to fp16 in SMEM (row sr = local_e*4+gate)
    for (int idx = tid; idx < NROWS * 1024; idx += RTHREADS){
        int sr = idx >> 10, wc = idx & 1023;
        int e = cta * HPC + (sr >> 2);
        int gate = sr & 3;
        unsigned val = 0u;
        if (e < HID){
            const float2 f2 = *(const float2*)(Whh + (size_t)(gate * HID + e) * HID + 2 * wc);
            unsigned lo = (unsigned)__half_as_ushort(__float2half_rn(f2.x));
            unsigned hi = (unsigned)__half_as_ushort(__float2half_rn(f2.y));
            val = (hi << 16) | lo;
        }
        smw32[sr * 1024 + wc] = val;
    }
    // zero all replicas of h buffer 0
    if (tid < HPC){
        int e = cta * HPC + tid;
        if (e < HID){
            #pragma unroll
            for (int k = 0; k < NCOPY; ++k) hbuf[k * HID + e] = 0.0f;
        }
    }
    __syncthreads();

    const int rowbase = w * RPW;                      // rows [7w, 7w+7)
    // pull K-half-0 of this warp's 7 rows into registers (loop-invariant)
    __half2 wreg[RPW][16];
    #pragma unroll
    for (int r = 0; r < RPW; ++r){
        #pragma unroll
        for (int j = 0; j < 8; ++j){
            uint2 wv = smW2[(rowbase + r) * 512 + l + 32 * j];
            wreg[r][2 * j]     = u2h2(wv.x);
            wreg[r][2 * j + 1] = u2h2(wv.y);
        }
    }

    if (tid == 0){
        red_release_add(bar);
        while (ld_acquire(bar) < (unsigned)NCTA) { }
    }
    __syncthreads();

    const int e0 = cta * HPC + 2 * w;                 // gate-phase elements (w<7)
    const int e1 = e0 + 1;
    const bool gw = (w < 7);
    const bool a0 = gw && (e0 < HID);
    const bool a1 = gw && (e1 < HID);
    const int mycopy = (cta + w) & (NCOPY - 1);
    float c0 = 0.0f, c1 = 0.0f;

    #pragma unroll 1
    for (int t = 0; t < TT; ++t){
        const float4* hr4 = (const float4*)(hbuf + ((size_t)(t & 1) * NCOPY + mycopy) * HID);
        float* hwb = hbuf + (size_t)((t + 1) & 1) * NCOPY * HID;

        // gate input projections (issued early; consumed after the dot)
        float gxe[8];
        #pragma unroll
        for (int g = 0; g < 4; ++g){
            gxe[g]     = a0 ? __ldcg(gx + (size_t)t * G4 + g * HID + e0) : 0.f;
            gxe[4 + g] = a1 ? __ldcg(gx + (size_t)t * G4 + g * HID + e1) : 0.f;
        }

        // batch A: h[0,1024) -> half2
        float4 hvA[8];
        #pragma unroll
        for (int j = 0; j < 8; ++j) hvA[j] = __ldcg(hr4 + l + 32 * j);
        // batch B loads issued early (consumed after chunks 0-1)
        float4 hvB[8];
        #pragma unroll
        for (int j = 0; j < 8; ++j) hvB[j] = __ldcg(hr4 + l + 32 * (j + 8));

        __half2 hhA[16];
        #pragma unroll
        for (int j = 0; j < 8; ++j){
            hhA[2 * j]     = __floats2half2_rn(hvA[j].x, hvA[j].y);
            hhA[2 * j + 1] = __floats2half2_rn(hvA[j].z, hvA[j].w);
        }

        float acc[RPW];
        #pragma unroll
        for (int r = 0; r < RPW; ++r) acc[r] = 0.0f;

        // chunks 0-1: register-resident W, h batch A
        #pragma unroll
        for (int ch = 0; ch < 2; ++ch){
            __half2 ha[RPW];
            #pragma unroll
            for (int r = 0; r < RPW; ++r) ha[r] = __halves2half2(__ushort_as_half(0), __ushort_as_half(0));
            #pragma unroll
            for (int jj = 0; jj < 4; ++jj){
                const int j = ch * 4 + jj;
                const __half2 h01 = hhA[2 * j], h23 = hhA[2 * j + 1];
                #pragma unroll
                for (int r = 0; r < RPW; ++r){
                    ha[r] = __hfma2(wreg[r][2 * j], h01, ha[r]);
                    ha[r] = __hfma2(wreg[r][2 * j + 1], h23, ha[r]);
                }
            }
            #pragma unroll
            for (int r = 0; r < RPW; ++r){
                float2 f2 = __half22float2(ha[r]);
                acc[r] += f2.x + f2.y;
            }
        }

        __half2 hhB[16];
        #pragma unroll
        for (int j = 0; j < 8; ++j){
            hhB[2 * j]     = __floats2half2_rn(hvB[j].x, hvB[j].y);
            hhB[2 * j + 1] = __floats2half2_rn(hvB[j].z, hvB[j].w);
        }

        // chunks 2-3: SMEM-streamed W, h batch B
        #pragma unroll
        for (int ch = 2; ch < 4; ++ch){
            __half2 ha[RPW];
            #pragma unroll
            for (int r = 0; r < RPW; ++r) ha[r] = __halves2half2(__ushort_as_half(0), __ushort_as_half(0));
            #pragma unroll
            for (int jj = 0; jj < 4; ++jj){
                const int j = ch * 4 + jj;           // 8..15
                const int jl = j - 8;
                const __half2 h01 = hhB[2 * jl], h23 = hhB[2 * jl + 1];
                #pragma unroll
                for (int r = 0; r < RPW; ++r){
                    uint2 wv = smW2[(rowbase + r) * 512 + l + 32 * j];
                    ha[r] = __hfma2(u2h2(wv.x), h01, ha[r]);
                    ha[r] = __hfma2(u2h2(wv.y), h23, ha[r]);
                }
            }
            #pragma unroll
            for (int r = 0; r < RPW; ++r){
                float2 f2 = __half22float2(ha[r]);
                acc[r] += f2.x + f2.y;
            }
        }

        // butterfly reduce 7 sums across the warp
        #pragma unroll
        for (int off = 16; off; off >>= 1){
            #pragma unroll
            for (int r = 0; r < RPW; ++r)
                acc[r] += __shfl_xor_sync(0xffffffffu, acc[r], off);
        }
        if (l == 0){
            #pragma unroll
            for (int r = 0; r < RPW; ++r) smSum[rowbase + r] = acc[r];
        }
        __syncthreads();

        // gate phase: warps 0-6 handle elements {2w, 2w+1}
        if (gw){
            float s[8];
            #pragma unroll
            for (int g = 0; g < 8; ++g) s[g] = smSum[8 * w + g];

            float ig0 = sigf(s[0] + gxe[0]);
            float fg0 = sigf(s[1] + gxe[1]);
            float gt0 = tanh_fast(s[2] + gxe[2]);
            float og0 = sigf(s[3] + gxe[3]);
            c0 = fg0 * c0 + ig0 * gt0;
            float hn0 = og0 * tanh_fast(c0);

            float ig1 = sigf(s[4] + gxe[4]);
            float fg1 = sigf(s[5] + gxe[5]);
            float gt1 = tanh_fast(s[6] + gxe[6]);
            float og1 = sigf(s[7] + gxe[7]);
            c1 = fg1 * c1 + ig1 * gt1;
            float hn1 = og1 * tanh_fast(c1);

            if (a0 && l < NCOPY)                  __stcg(&hwb[l * HID + e0], hn0);
            if (a1 && l >= NCOPY && l < 2*NCOPY)  __stcg(&hwb[(l - NCOPY) * HID + e1], hn1);
            if (a0 && l == 0) __stcg(&hs[(size_t)t * HID + e0], __float2half(hn0));
            if (a1 && l == 1) __stcg(&hs[(size_t)t * HID + e1], __float2half(hn1));
        }

        // grid barrier: release-arrive; 4-deep unrolled acquire-poll
        __syncthreads();
        if (tid == 0){
            red_release_add(bar);
            const unsigned target = (unsigned)(t + 2) * (unsigned)NCTA;
            unsigned v;
            do {
                unsigned p0 = ld_acquire(bar);
                unsigned p1 = ld_acquire(bar);
                unsigned p2 = ld_acquire(bar);
                unsigned p3 = ld_acquire(bar);
                v = p0 > p1 ? p0 : p1;
                if (p2 > v) v = p2;
                if (p3 > v) v = p3;
            } while (v < target);
        }
        __syncthreads();
    }
}

// ---------------- launch ----------------
extern "C" void kernel_launch(void* const* d_in, const int* in_sizes, int n_in,
                              void* d_out, int out_size){
    const float* x    = (const float*)d_in[0];
    const float* W_ih = (const float*)d_in[1];
    const float* W_hh = (const float*)d_in[2];
    const float* b_ih = (const float*)d_in[3];
    const float* b_hh = (const float*)d_in[4];
    const float* Wo   = (const float*)d_in[5];
    const float* bo   = (const float*)d_in[6];
    float* out = (float*)d_out;

    unsigned char* base = nullptr;
    cudaGetSymbolAddress((void**)&base, g_scratch);
    float*    gx   = (float*)(base + OFF_GX);
    __half*   xh   = (__half*)(base + OFF_XH);
    __half*   xl   = (__half*)(base + OFF_XL);
    __half*   wih  = (__half*)(base + OFF_WIH);
    __half*   wil  = (__half*)(base + OFF_WIL);
    __half*   wo   = (__half*)(base + OFF_WO);
    __half*   hsb  = (__half*)(base + OFF_HS);
    float*    bias = (float*)(base + OFF_BIAS);
    float*    hbuf = (float*)(base + OFF_HBUF);
    unsigned* bar  = (unsigned*)(base + OFF_BAR);

    cudaFuncSetAttribute(lstm_rec_kernel,
                         cudaFuncAttributeMaxDynamicSharedMemorySize, REC_SMEM);

    setup_kernel<<<G4 / 256, 256>>>(b_ih, b_hh, bias, bar);
    f2h_split_kernel<<<1024, 256>>>(x,    xh,  xl,  TT * INW);
    f2h_split_kernel<<<1024, 256>>>(W_ih, wih, wil, G4 * INW);
    // Wo: lo residual not needed; dump into gx region, which GEMM #1 below
    // fully overwrites afterwards (same stream => ordered).
    f2h_split_kernel<<<1024, 256>>>(Wo, wo, (__half*)gx, INW * HID);

    dim3 g1(G4 / 128, TT / 128);
    gemm_nt_kernel<0, 0><<<g1, 256>>>(xh, wih, bias, gx, TT, G4, INW);
    gemm_nt_kernel<0, 1><<<g1, 256>>>(xl, wih, bias, gx, TT, G4, INW);
    gemm_nt_kernel<0, 1><<<g1, 256>>>(xh, wil, bias, gx, TT, G4, INW);

    lstm_rec_kernel<<<NCTA, RTHREADS, REC_SMEM>>>(W_hh, gx, hsb, hbuf, bar);

    dim3 g2(INW / 128, TT / 128);
    gemm_nt_kernel<1, 0><<<g2, 256>>>(hsb, wo, bo, out, TT, INW, HID);
}